// round 1
// baseline (speedup 1.0000x reference)
#include <cuda_runtime.h>
#include <mma.h>
using namespace nvcuda;

// Problem dims
#define BB 16
#define LL 50
#define PP 49
#define TT 20
#define DD 512
#define HH 8
#define DHD 64
#define DFF 2048
#define NBL (BB*LL)          // 800
#define M_IMG (NBL*TT)       // 16000
#define M_TIT (NBL*PP)       // 39200
#define M_TIT_PAD 39232      // padded to multiple of 64

// Scratch (device globals are zero-initialized; padded rows are never written -> stay 0)
__device__ float g_attnI[(size_t)M_IMG*DD];
__device__ float g_attnT[(size_t)M_TIT_PAD*DD];
__device__ float g_hidI[(size_t)M_IMG*DD];
__device__ float g_hidT[(size_t)M_TIT_PAD*DD];
__device__ float g_G[(size_t)M_TIT_PAD*DFF];
__device__ float g_FI[(size_t)M_IMG*DD];
__device__ float g_FT[(size_t)M_TIT_PAD*DD];

// ---------------------------------------------------------------------------
// Attention kernel: one block per (bl, h). Exact fp32.
// ---------------------------------------------------------------------------
__global__ void __launch_bounds__(256) attn_kernel(
    const float* __restrict__ img, const float* __restrict__ tit,
    const int* __restrict__ mask,
    const float* __restrict__ scale_img, const float* __restrict__ scale_tit,
    float* __restrict__ attnI, float* __restrict__ attnT)
{
    __shared__ float simg[PP][DHD+1];
    __shared__ float stit[TT][DHD+1];
    __shared__ float raw[PP][TT];
    __shared__ float pimg[PP][TT];
    __shared__ float ptit[TT][PP];
    __shared__ float sci[PP];
    __shared__ float sct[TT];
    __shared__ int   smask[TT];

    int bl = blockIdx.x >> 3;
    int h  = blockIdx.x & 7;
    int tid = threadIdx.x;

    const float* ib = img + (size_t)bl*PP*DD + h*DHD;
    const float* tb = tit + (size_t)bl*TT*DD + h*DHD;

    for (int i = tid; i < PP*DHD; i += 256) { int p=i>>6, d=i&63; simg[p][d] = ib[p*DD+d]; }
    for (int i = tid; i < TT*DHD; i += 256) { int t=i>>6, d=i&63; stit[t][d] = tb[t*DD+d]; }
    if (tid < TT) { smask[tid] = mask[bl*TT+tid]; sct[tid] = scale_tit[h*TT+tid]; }
    if (tid >= 64 && tid < 64+PP) sci[tid-64] = scale_img[h*PP + (tid-64)];
    __syncthreads();

    // raw[p][t] = <img_p, tit_t> / 8
    for (int i = tid; i < PP*TT; i += 256) {
        int p = i / TT, t = i - p*TT;
        float s = 0.f;
        #pragma unroll
        for (int d = 0; d < DHD; d++) s += simg[p][d]*stit[t][d];
        raw[p][t] = s * 0.125f;
    }
    __syncthreads();

    // softmaxes
    if (tid < PP) {
        int p = tid; float sc = sci[p];
        float v[TT]; float mx = -INFINITY;
        #pragma unroll
        for (int t = 0; t < TT; t++) { v[t] = smask[t] ? raw[p][t]*sc : -1e9f; mx = fmaxf(mx, v[t]); }
        float sum = 0.f;
        #pragma unroll
        for (int t = 0; t < TT; t++) { v[t] = __expf(v[t]-mx); sum += v[t]; }
        float inv = 1.f/sum;
        #pragma unroll
        for (int t = 0; t < TT; t++) pimg[p][t] = v[t]*inv;
    } else if (tid >= 64 && tid < 64+TT) {
        int t = tid-64; float sc = sct[t];
        if (smask[t]) {
            float mx = -INFINITY;
            for (int p = 0; p < PP; p++) mx = fmaxf(mx, raw[p][t]*sc);
            float sum = 0.f;
            for (int p = 0; p < PP; p++) { float e = __expf(raw[p][t]*sc - mx); ptit[t][p] = e; sum += e; }
            float inv = 1.f/sum;
            for (int p = 0; p < PP; p++) ptit[t][p] *= inv;
        } else {
            float u = 1.0f/(float)PP;   // all -1e9 -> uniform softmax
            for (int p = 0; p < PP; p++) ptit[t][p] = u;
        }
    }
    __syncthreads();

    // hid_img[t][d] = sum_p ptit[t][p]*img[p][d]
    for (int i = tid; i < TT*DHD; i += 256) {
        int t = i>>6, d = i&63;
        float s = 0.f;
        #pragma unroll
        for (int p = 0; p < PP; p++) s += ptit[t][p]*simg[p][d];
        attnI[((size_t)bl*TT + t)*DD + h*DHD + d] = s;
    }
    // hid_tit[p][d] = sum_t pimg[p][t]*tit[t][d]
    for (int i = tid; i < PP*DHD; i += 256) {
        int p = i>>6, d = i&63;
        float s = 0.f;
        #pragma unroll
        for (int t = 0; t < TT; t++) s += pimg[p][t]*stit[t][d];
        attnT[((size_t)bl*PP + p)*DD + h*DHD + d] = s;
    }
}

// ---------------------------------------------------------------------------
// tf32 WMMA GEMM: C[M,N] = A[M,K] @ W[N,K]^T + bias (optional gelu epilogue)
// BM=64 BN=128 BK=32, 8 warps (2x4), each warp 32x32.
// M % 64 == 0, N % 128 == 0, K % 32 == 0 (guaranteed by padding).
// ---------------------------------------------------------------------------
#define BM 64
#define BN 128
#define BK 32
#define AST 40   // smem leading dim (multiple of 4)
#define CST 20

__device__ __forceinline__ float gelu_tanh_f(float x) {
    return 0.5f*x*(1.f + tanhf(0.79788456080286536f*(x + 0.044715f*x*x*x)));
}

template<int GELU_EPI>
__global__ void __launch_bounds__(256) gemm_tf32(
    const float* __restrict__ A, const float* __restrict__ W,
    const float* __restrict__ bias, float* __restrict__ C,
    int M, int N, int K)
{
    __shared__ float As[BM*AST];
    __shared__ float Bs[BN*AST];
    __shared__ float Cs[8*16*CST];

    int tid = threadIdx.x;
    int warp = tid >> 5, lane = tid & 31;
    int wm = warp >> 2, wn = warp & 3;
    long m0 = (long)blockIdx.y * BM;
    long n0 = (long)blockIdx.x * BN;

    wmma::fragment<wmma::accumulator,16,16,8,float> acc[2][2];
    #pragma unroll
    for (int i = 0; i < 2; i++)
        #pragma unroll
        for (int j = 0; j < 2; j++) wmma::fill_fragment(acc[i][j], 0.f);

    for (int k0 = 0; k0 < K; k0 += BK) {
        // A tile: 64x32 = 512 float4 loads
        #pragma unroll
        for (int r = 0; r < 2; r++) {
            int idx = tid + r*256;
            int row = idx >> 3, c = (idx & 7) << 2;
            float4 v = *(const float4*)(A + (m0+row)*(long)K + k0 + c);
            *(float4*)(As + row*AST + c) = v;
        }
        // B tile: 128x32 = 1024 float4 loads
        #pragma unroll
        for (int r = 0; r < 4; r++) {
            int idx = tid + r*256;
            int row = idx >> 3, c = (idx & 7) << 2;
            float4 v = *(const float4*)(W + (n0+row)*(long)K + k0 + c);
            *(float4*)(Bs + row*AST + c) = v;
        }
        __syncthreads();

        #pragma unroll
        for (int kk = 0; kk < BK; kk += 8) {
            wmma::fragment<wmma::matrix_a,16,16,8,wmma::precision::tf32,wmma::row_major> af[2];
            wmma::fragment<wmma::matrix_b,16,16,8,wmma::precision::tf32,wmma::col_major> bf[2];
            #pragma unroll
            for (int i = 0; i < 2; i++) {
                wmma::load_matrix_sync(af[i], As + (wm*32 + i*16)*AST + kk, AST);
                #pragma unroll
                for (int e = 0; e < af[i].num_elements; e++)
                    af[i].x[e] = wmma::__float_to_tf32(af[i].x[e]);
            }
            #pragma unroll
            for (int j = 0; j < 2; j++) {
                wmma::load_matrix_sync(bf[j], Bs + (wn*32 + j*16)*AST + kk, AST);
                #pragma unroll
                for (int e = 0; e < bf[j].num_elements; e++)
                    bf[j].x[e] = wmma::__float_to_tf32(bf[j].x[e]);
            }
            #pragma unroll
            for (int i = 0; i < 2; i++)
                #pragma unroll
                for (int j = 0; j < 2; j++)
                    wmma::mma_sync(acc[i][j], af[i], bf[j], acc[i][j]);
        }
        __syncthreads();
    }

    // Epilogue via per-warp smem staging (bias + optional gelu)
    float* cw = Cs + warp*16*CST;
    #pragma unroll
    for (int i = 0; i < 2; i++) {
        #pragma unroll
        for (int j = 0; j < 2; j++) {
            wmma::store_matrix_sync(cw, acc[i][j], CST, wmma::mem_row_major);
            __syncwarp();
            long gm = m0 + wm*32 + i*16;
            long gn = n0 + wn*32 + j*16;
            #pragma unroll
            for (int q = 0; q < 8; q++) {
                int idx = lane + q*32;
                int r = idx >> 4, c = idx & 15;
                float v = cw[r*CST + c] + bias[gn + c];
                if (GELU_EPI) v = gelu_tanh_f(v);
                C[(gm + r)*(long)N + gn + c] = v;
            }
            __syncwarp();
        }
    }
}

// ---------------------------------------------------------------------------
// LayerNorm (ddof=1) + residual: out = hid + a*(x-mean)/(std+eps) + b
// ---------------------------------------------------------------------------
__global__ void __launch_bounds__(128) ln_res_kernel(
    const float* __restrict__ F, const float* __restrict__ hid,
    const float* __restrict__ a, const float* __restrict__ b,
    float* __restrict__ out)
{
    int row = blockIdx.x;
    const float* x = F + (size_t)row*DD;
    int tid = threadIdx.x;
    float v[4]; float s = 0.f, ss = 0.f;
    #pragma unroll
    for (int k = 0; k < 4; k++) { v[k] = x[tid + k*128]; s += v[k]; ss += v[k]*v[k]; }
    #pragma unroll
    for (int o = 16; o; o >>= 1) { s += __shfl_xor_sync(~0u, s, o); ss += __shfl_xor_sync(~0u, ss, o); }
    __shared__ float sh[8];
    if ((tid & 31) == 0) { sh[tid>>5] = s; sh[4 + (tid>>5)] = ss; }
    __syncthreads();
    s  = sh[0]+sh[1]+sh[2]+sh[3];
    ss = sh[4]+sh[5]+sh[6]+sh[7];
    float mean = s * (1.f/512.f);
    float var  = fmaxf((ss - 512.f*mean*mean) * (1.f/511.f), 0.f);
    float inv  = 1.f/(sqrtf(var) + 1e-6f);
    const float* hh = hid + (size_t)row*DD;
    float* oo = out + (size_t)row*DD;
    #pragma unroll
    for (int k = 0; k < 4; k++) {
        int c = tid + k*128;
        oo[c] = hh[c] + a[c]*(v[k]-mean)*inv + b[c];
    }
}

// ---------------------------------------------------------------------------
// Launch
// ---------------------------------------------------------------------------
extern "C" void kernel_launch(void* const* d_in, const int* in_sizes, int n_in,
                              void* d_out, int out_size)
{
    const float* img         = (const float*)d_in[0];
    const float* title       = (const float*)d_in[1];
    const int*   mask        = (const int*)  d_in[2];
    const float* scale_img   = (const float*)d_in[3];
    const float* scale_title = (const float*)d_in[4];
    const float* w_proj      = (const float*)d_in[5];
    const float* b_proj      = (const float*)d_in[6];
    const float* w1_img      = (const float*)d_in[7];
    const float* b1_img      = (const float*)d_in[8];
    const float* w2_img      = (const float*)d_in[9];
    const float* b2_img      = (const float*)d_in[10];
    const float* w1_tit      = (const float*)d_in[11];
    const float* b1_tit      = (const float*)d_in[12];
    const float* w2_tit      = (const float*)d_in[13];
    const float* b2_tit      = (const float*)d_in[14];
    const float* ln_a_img    = (const float*)d_in[15];
    const float* ln_b_img    = (const float*)d_in[16];
    const float* ln_a_tit    = (const float*)d_in[17];
    const float* ln_b_tit    = (const float*)d_in[18];
    float* out = (float*)d_out;

    float *attnI, *attnT, *hidI, *hidT, *G, *FI, *FT;
    cudaGetSymbolAddress((void**)&attnI, g_attnI);
    cudaGetSymbolAddress((void**)&attnT, g_attnT);
    cudaGetSymbolAddress((void**)&hidI,  g_hidI);
    cudaGetSymbolAddress((void**)&hidT,  g_hidT);
    cudaGetSymbolAddress((void**)&G,     g_G);
    cudaGetSymbolAddress((void**)&FI,    g_FI);
    cudaGetSymbolAddress((void**)&FT,    g_FT);

    attn_kernel<<<NBL*HH, 256>>>(img, title, mask, scale_img, scale_title, attnI, attnT);

    // proj: hid = attn @ w_proj^T + b_proj
    gemm_tf32<0><<<dim3(DD/BN,  M_IMG/BM),     256>>>(attnI, w_proj, b_proj, hidI, M_IMG,     DD,  DD);
    gemm_tf32<0><<<dim3(DD/BN,  M_TIT_PAD/BM), 256>>>(attnT, w_proj, b_proj, hidT, M_TIT_PAD, DD,  DD);

    // img FFN
    gemm_tf32<1><<<dim3(DFF/BN, M_IMG/BM),     256>>>(hidI, w1_img, b1_img, G,  M_IMG,     DFF, DD);
    gemm_tf32<0><<<dim3(DD/BN,  M_IMG/BM),     256>>>(G,    w2_img, b2_img, FI, M_IMG,     DD,  DFF);
    // tit FFN (reuses G)
    gemm_tf32<1><<<dim3(DFF/BN, M_TIT_PAD/BM), 256>>>(hidT, w1_tit, b1_tit, G,  M_TIT_PAD, DFF, DD);
    gemm_tf32<0><<<dim3(DD/BN,  M_TIT_PAD/BM), 256>>>(G,    w2_tit, b2_tit, FT, M_TIT_PAD, DD,  DFF);

    // LN + residual -> outputs (out_img then out_tit, flat)
    ln_res_kernel<<<M_IMG, 128>>>(FI, hidI, ln_a_img, ln_b_img, out);
    ln_res_kernel<<<M_TIT, 128>>>(FT, hidT, ln_a_tit, ln_b_tit, out + (size_t)M_IMG*DD);
}